// round 1
// baseline (speedup 1.0000x reference)
#include <cuda_runtime.h>

#define HW 196
#define IMW 14

// Scratch buffers (no cudaMalloc allowed): 128*256*196 floats each = 25.7 MB
__device__ float g_out1[128 * 256 * HW];
__device__ float g_out2[128 * 256 * HW];

// Implicit-GEMM conv kernel.
//   C[m, col] = sum_k A[m, k] * B(k, col)   (+ biases / epilogue)
// col = n*196 + hw over all 128 images.
// CONV3x3=false: B(k, col) = Bsrc[n*Cin*HW + k*HW + hw] + inb        (1x1 conv)
// CONV3x3=true : k = ci*9 + (dh*3+dw);  B = masked 3x3 stencil + inb (3x3 pad 1)
// RESID: epilogue v = relu((acc+outb)*rs + rb + x[n, m, hw]) ; else v = acc+outb
template<bool CONV3x3, bool RESID>
__global__ __launch_bounds__(256)
void conv_gemm(const float* __restrict__ A, const float* __restrict__ Bsrc,
               float* __restrict__ C, const float* __restrict__ Xres,
               int K, int Cin, int Cout,
               const float* inb_ptr, const float* outb_ptr,
               const float* rs_ptr, const float* rb_ptr)
{
    const int tid  = threadIdx.x;
    const int tx   = tid & 15;        // 0..15 -> 8 output cols each
    const int ty   = tid >> 4;        // 0..15 -> 8 output rows each
    const int m0   = blockIdx.y << 7; // 128-row tile
    const int col0 = blockIdx.x << 7; // 128-col tile (25088/128 = 196 exact)

    __shared__ __align__(16) float As[8][128];
    __shared__ __align__(16) float Bs[8][128];

    const float inb  = inb_ptr  ? *inb_ptr  : 0.f;
    const float outb = outb_ptr ? *outb_ptr : 0.f;

    // A tile load mapping: 128 rows x 8 k, one float4 per thread
    const int arow = tid >> 1;
    const int acol = (tid & 1) << 2;
    const float* Ap = A + (m0 + arow) * K + acol;

    // B tile load mapping: 8 k-rows x 128 cols, 4 scalar loads per thread
    const int brow = tid >> 5;
    const int bc0  = tid & 31;
    int b_base[4], b_h[4], b_w[4];
#pragma unroll
    for (int j = 0; j < 4; j++) {
        int col = col0 + bc0 + (j << 5);
        int n   = col / HW;
        int hw  = col - n * HW;
        if (CONV3x3) {
            b_base[j] = n * Cin * HW;
            b_h[j]    = hw / IMW;
            b_w[j]    = hw - b_h[j] * IMW;
        } else {
            b_base[j] = n * Cin * HW + hw;
        }
    }

    auto loadB = [&](int k, int j) -> float {
        if (!CONV3x3) {
            return Bsrc[b_base[j] + k * HW] + inb;
        } else {
            int ci  = k / 9;
            int tap = k - ci * 9;
            int dh  = tap / 3;
            int dw  = tap - dh * 3;
            int hh  = b_h[j] + dh - 1;
            int ww  = b_w[j] + dw - 1;
            if ((unsigned)hh < IMW && (unsigned)ww < IMW)
                return Bsrc[b_base[j] + ci * HW + hh * IMW + ww] + inb;
            return 0.f;  // zero padding (bias added pre-pad in reference)
        }
    };

    float acc[8][8];
#pragma unroll
    for (int i = 0; i < 8; i++)
#pragma unroll
        for (int j = 0; j < 8; j++) acc[i][j] = 0.f;

    // ---- load first tile ----
    {
        float4 a4 = *(const float4*)Ap;
        As[acol + 0][arow] = a4.x;
        As[acol + 1][arow] = a4.y;
        As[acol + 2][arow] = a4.z;
        As[acol + 3][arow] = a4.w;
#pragma unroll
        for (int j = 0; j < 4; j++)
            Bs[brow][bc0 + (j << 5)] = loadB(brow, j);
    }
    __syncthreads();

    const int nk = K >> 3;
    for (int kt = 1; kt <= nk; kt++) {
        float4 a4;
        float  bv[4];
        const bool more = (kt < nk);
        if (more) {
            const int k0 = kt << 3;
            a4 = *(const float4*)(Ap + k0);
#pragma unroll
            for (int j = 0; j < 4; j++)
                bv[j] = loadB(k0 + brow, j);
        }
        // compute current smem tile
#pragma unroll
        for (int kk = 0; kk < 8; kk++) {
            float a[8], b[8];
            *(float4*)(a)     = *(const float4*)&As[kk][(ty << 3)];
            *(float4*)(a + 4) = *(const float4*)&As[kk][(ty << 3) + 4];
            *(float4*)(b)     = *(const float4*)&Bs[kk][(tx << 3)];
            *(float4*)(b + 4) = *(const float4*)&Bs[kk][(tx << 3) + 4];
#pragma unroll
            for (int i = 0; i < 8; i++)
#pragma unroll
                for (int j = 0; j < 8; j++)
                    acc[i][j] = fmaf(a[i], b[j], acc[i][j]);
        }
        __syncthreads();
        if (more) {
            As[acol + 0][arow] = a4.x;
            As[acol + 1][arow] = a4.y;
            As[acol + 2][arow] = a4.z;
            As[acol + 3][arow] = a4.w;
#pragma unroll
            for (int j = 0; j < 4; j++)
                Bs[brow][bc0 + (j << 5)] = bv[j];
        }
        __syncthreads();
    }

    // ---- epilogue ----
    const float rs = RESID ? *rs_ptr : 1.f;
    const float rb = RESID ? *rb_ptr : 0.f;
#pragma unroll
    for (int j = 0; j < 8; j++) {
        int col = col0 + (tx << 3) + j;
        int n   = col / HW;
        int hw  = col - n * HW;
        float* cp = C + n * Cout * HW + (m0 + (ty << 3)) * HW + hw;
        const float* xp = RESID
            ? (Xres + n * 1024 * HW + (m0 + (ty << 3)) * HW + hw) : nullptr;
#pragma unroll
        for (int i = 0; i < 8; i++) {
            float v = acc[i][j] + outb;
            if (RESID) {
                v = fmaf(v, rs, rb) + xp[i * HW];
                v = fmaxf(v, 0.f);
            }
            cp[i * HW] = v;
        }
    }
}

extern "C" void kernel_launch(void* const* d_in, const int* in_sizes, int n_in,
                              void* d_out, int out_size)
{
    const float* x   = (const float*)d_in[0];   // [128,1024,14,14]
    const float* w1  = (const float*)d_in[1];   // [256,1024,1,1]
    const float* w2  = (const float*)d_in[2];   // [256,256,3,3]
    const float* w3  = (const float*)d_in[3];   // [1024,256,1,1]
    const float* b1b = (const float*)d_in[4];
    const float* b2a = (const float*)d_in[5];
    const float* b2b = (const float*)d_in[6];
    const float* b3a = (const float*)d_in[7];
    const float* b3b = (const float*)d_in[8];
    const float* rsc = (const float*)d_in[9];
    const float* rbi = (const float*)d_in[10];
    float* out = (float*)d_out;

    float *o1, *o2;
    cudaGetSymbolAddress((void**)&o1, g_out1);
    cudaGetSymbolAddress((void**)&o2, g_out2);

    dim3 block(256);
    // conv1: 1x1, 1024 -> 256, out bias b1b
    conv_gemm<false, false><<<dim3(196, 2), block>>>(
        w1, x, o1, nullptr, 1024, 1024, 256, nullptr, b1b, nullptr, nullptr);
    // conv2: 3x3 pad1, 256 -> 256, in bias b2a, out bias b2b
    conv_gemm<true, false><<<dim3(196, 2), block>>>(
        w2, o1, o2, nullptr, 2304, 256, 256, b2a, b2b, nullptr, nullptr);
    // conv3: 1x1, 256 -> 1024, in bias b3a, out bias b3b, fused residual ReLU
    conv_gemm<false, true><<<dim3(196, 8), block>>>(
        w3, o2, out, x, 256, 256, 1024, b3a, b3b, rsc, rbi);
}

// round 3
// speedup vs baseline: 2.2460x; 2.2460x over previous
#include <cuda_runtime.h>
#include <cstdint>

#define NHW 196
#define SPT 25088   // 128 * 196

// ---------------- scratch (no cudaMalloc allowed) ----------------
__device__ float g_xt[(size_t)SPT * 1024];   // x in NHWC
__device__ float g_o1[(size_t)SPT * 256];    // conv1 out (+b1b+b2a), NHWC
__device__ float g_o2[(size_t)SPT * 256];    // conv2 out (+b2b+b3a), NHWC
__device__ float g_w2t[256 * 2304];          // w2 as [co][tap*256+ci]

// ---------------- helpers ----------------
__device__ __forceinline__ uint32_t smem_u32(const void* p) {
    uint32_t a;
    asm("{ .reg .u64 t; cvta.to.shared.u64 t, %1; cvt.u32.u64 %0, t; }"
        : "=r"(a) : "l"(p));
    return a;
}

// pack two fp32 -> bf16x2, x in low half, y in high half
__device__ __forceinline__ uint32_t packbf(float x, float y) {
    uint32_t d;
    asm("cvt.rn.bf16x2.f32 %0, %1, %2;" : "=r"(d) : "f"(y), "f"(x));
    return d;
}

// fp32x4 -> hi bf16x2x2 + lo bf16x2x2 (exact residual split)
__device__ __forceinline__ void split4(float4 v, uint2& h, uint2& l) {
    h.x = packbf(v.x, v.y);
    h.y = packbf(v.z, v.w);
    float hx = __uint_as_float(h.x << 16);
    float hy = __uint_as_float(h.x & 0xffff0000u);
    float hz = __uint_as_float(h.y << 16);
    float hw = __uint_as_float(h.y & 0xffff0000u);
    l.x = packbf(v.x - hx, v.y - hy);
    l.y = packbf(v.z - hz, v.w - hw);
}

__device__ __forceinline__ void ldsm4(uint32_t& r0, uint32_t& r1,
                                      uint32_t& r2, uint32_t& r3, uint32_t a) {
    asm volatile("ldmatrix.sync.aligned.m8n8.x4.shared.b16 {%0,%1,%2,%3}, [%4];"
                 : "=r"(r0), "=r"(r1), "=r"(r2), "=r"(r3) : "r"(a));
}
__device__ __forceinline__ void ldsm2(uint32_t& r0, uint32_t& r1, uint32_t a) {
    asm volatile("ldmatrix.sync.aligned.m8n8.x2.shared.b16 {%0,%1}, [%2];"
                 : "=r"(r0), "=r"(r1) : "r"(a));
}
__device__ __forceinline__ void mma16816(float* c, const uint32_t* a, const uint32_t* b) {
    asm volatile("mma.sync.aligned.m16n8k16.row.col.f32.bf16.bf16.f32 "
                 "{%0,%1,%2,%3}, {%4,%5,%6,%7}, {%8,%9}, {%0,%1,%2,%3};"
                 : "+f"(c[0]), "+f"(c[1]), "+f"(c[2]), "+f"(c[3])
                 : "r"(a[0]), "r"(a[1]), "r"(a[2]), "r"(a[3]), "r"(b[0]), "r"(b[1]));
}

// ---------------- transposes ----------------
__global__ void transpose_x(const float* __restrict__ x, float* __restrict__ xt) {
    __shared__ float tile[32][33];
    int n = blockIdx.z, c0 = blockIdx.y * 32, hw0 = blockIdx.x * 32;
    int tx = threadIdx.x, ty = threadIdx.y;
#pragma unroll
    for (int i = 0; i < 4; i++) {
        int hw = hw0 + tx;
        if (hw < NHW)
            tile[ty + 8 * i][tx] = x[((size_t)n * 1024 + c0 + ty + 8 * i) * NHW + hw];
    }
    __syncthreads();
#pragma unroll
    for (int i = 0; i < 4; i++) {
        int hw = hw0 + ty + 8 * i;
        if (hw < NHW)
            xt[((size_t)n * NHW + hw) * 1024 + c0 + tx] = tile[tx][ty + 8 * i];
    }
}

__global__ void transpose_w2(const float* __restrict__ w2, float* __restrict__ w2t) {
    int i = blockIdx.x * 256 + threadIdx.x;  // 589824 elements
    int co = i / 2304, r = i - co * 2304;
    int ci = r / 9, tap = r - ci * 9;
    w2t[co * 2304 + tap * 256 + ci] = w2[i];
}

// ---------------- SMEM layout per stage (40960 B) ----------------
// A_hi[128 rows x 80B]  @0      A_lo @10240
// B_hi                  @20480  B_lo @30720
// two stages = 81920 B; conv3 bounce tile (128 x 133 fp32) reuses it.
static constexpr int STAGE = 40960;
static constexpr int SMEM_BYTES = 2 * STAGE;

// ---------------- main mma conv kernel ----------------
// D[sp 128, co 128] = Act[sp, K] * W[co, K]^T  (+ fused biases / residual)
template <int CONV>
__global__ __launch_bounds__(256, 1)
void conv_mma(const float* __restrict__ act, const float* __restrict__ wgt,
              float* __restrict__ out, const float* __restrict__ xres,
              const float* __restrict__ pa, const float* __restrict__ pb,
              const float* __restrict__ pc) {
    constexpr int K   = (CONV == 1) ? 1024 : (CONV == 2) ? 2304 : 256;
    constexpr int NKB = K / 32;
    constexpr int NB  = (CONV == 3) ? 8 : 2;

    extern __shared__ __align__(16) char smem[];
    const uint32_t sb = smem_u32(smem);
    const int tid  = threadIdx.x;
    const int lane = tid & 31, w = tid >> 5;
    const int wm = w >> 2, wn = w & 3;

    const int bid = blockIdx.x;
    const int mt_ = bid / NB;
    const int co0 = (bid - mt_ * NB) * 128;
    const int sp0 = mt_ * 128;

    // per-thread global-load coords: row r (0..127), k-half kh (16 floats)
    const int r  = tid >> 1;
    const int kh = tid & 1;
    int an = 0, ahh = 0, aww = 0;
    if (CONV == 2) {
        int sp = sp0 + r;
        an = sp / NHW;
        int rem = sp - an * NHW;
        ahh = rem / 14;
        aww = rem - ahh * 14;
    }

    float4 pA[4], pB[4];
    auto loadAB = [&](int kb) {
        if (CONV == 2) {
            int tap = kb >> 3;
            int dh = tap / 3 - 1, dw = tap - (tap / 3) * 3 - 1;
            int hh = ahh + dh, ww = aww + dw;
            bool ok = ((unsigned)hh < 14u) && ((unsigned)ww < 14u);
            const float* p = act + ((size_t)(an * NHW + hh * 14 + ww)) * 256 +
                             (kb & 7) * 32 + kh * 16;
#pragma unroll
            for (int i = 0; i < 4; i++)
                pA[i] = ok ? *(const float4*)(p + 4 * i) : make_float4(0.f, 0.f, 0.f, 0.f);
        } else {
            const float* p = act + (size_t)(sp0 + r) * K + kb * 32 + kh * 16;
#pragma unroll
            for (int i = 0; i < 4; i++) pA[i] = *(const float4*)(p + 4 * i);
        }
        const float* q = wgt + (size_t)(co0 + r) * K + kb * 32 + kh * 16;
#pragma unroll
        for (int i = 0; i < 4; i++) pB[i] = *(const float4*)(q + 4 * i);
    };

    auto stsAB = [&](int s) {
        char* st = smem + s * STAGE;
        const uint32_t ro = (uint32_t)r * 80 + (uint32_t)kh * 32;
#pragma unroll
        for (int i = 0; i < 4; i++) {
            uint2 h, l;
            split4(pA[i], h, l);
            *(uint2*)(st + ro + 8 * i)         = h;
            *(uint2*)(st + 10240 + ro + 8 * i) = l;
            split4(pB[i], h, l);
            *(uint2*)(st + 20480 + ro + 8 * i) = h;
            *(uint2*)(st + 30720 + ro + 8 * i) = l;
        }
    };

    float acc[4][4][4];
#pragma unroll
    for (int i = 0; i < 4; i++)
#pragma unroll
        for (int j = 0; j < 4; j++)
#pragma unroll
            for (int q = 0; q < 4; q++) acc[i][j][q] = 0.f;

    // ldmatrix per-lane byte offsets (relative to matrix base)
    const uint32_t a_off = (uint32_t)(wm * 64 + (lane & 15)) * 80 + (((uint32_t)lane >> 4) << 4);
    const int lb = lane & 15;
    const uint32_t b_off = (uint32_t)(wn * 32 + (lb & 7)) * 80 + (((uint32_t)lb >> 3) << 4);

    auto compute = [&](int s) {
        const uint32_t st = sb + s * STAGE;
#pragma unroll
        for (int ks = 0; ks < 2; ks++) {
            uint32_t Ah[4][4], Al[4][4], Bh[4][2], Bl[4][2];
#pragma unroll
            for (int mt = 0; mt < 4; mt++) {
                uint32_t ad = st + a_off + mt * (16 * 80) + ks * 32;
                ldsm4(Ah[mt][0], Ah[mt][1], Ah[mt][2], Ah[mt][3], ad);
                ldsm4(Al[mt][0], Al[mt][1], Al[mt][2], Al[mt][3], ad + 10240);
            }
#pragma unroll
            for (int nt = 0; nt < 4; nt++) {
                uint32_t bd = st + 20480 + b_off + nt * (8 * 80) + ks * 32;
                ldsm2(Bh[nt][0], Bh[nt][1], bd);
                ldsm2(Bl[nt][0], Bl[nt][1], bd + 10240);
            }
#pragma unroll
            for (int mt = 0; mt < 4; mt++)
#pragma unroll
                for (int nt = 0; nt < 4; nt++) {
                    mma16816(acc[mt][nt], Ah[mt], Bh[nt]);
                    mma16816(acc[mt][nt], Ah[mt], Bl[nt]);
                    mma16816(acc[mt][nt], Al[mt], Bh[nt]);
                }
        }
    };

    // ---- pipeline ----
    loadAB(0);
    stsAB(0);
    __syncthreads();
    for (int kb = 0; kb < NKB; kb++) {
        if (kb + 1 < NKB) loadAB(kb + 1);
        compute(kb & 1);
        __syncthreads();
        if (kb + 1 < NKB) {
            stsAB((kb + 1) & 1);
            __syncthreads();
        }
    }

    // ---- epilogue ----
    const int g = lane >> 2, t2 = (lane & 3) * 2;
    if (CONV != 3) {
        const float ob = pa[0] + pb[0];
#pragma unroll
        for (int mt = 0; mt < 4; mt++) {
            int row = sp0 + wm * 64 + mt * 16 + g;
#pragma unroll
            for (int nt = 0; nt < 4; nt++) {
                int col = co0 + wn * 32 + nt * 8 + t2;
                float2 v0 = make_float2(acc[mt][nt][0] + ob, acc[mt][nt][1] + ob);
                float2 v1 = make_float2(acc[mt][nt][2] + ob, acc[mt][nt][3] + ob);
                *(float2*)&out[(size_t)row * 256 + col]       = v0;
                *(float2*)&out[(size_t)(row + 8) * 256 + col] = v1;
            }
        }
    } else {
        const float ob = pa[0], rs = pb[0], rb = pc[0];
        float* bn = (float*)smem;   // 128 x 133 fp32 bounce tile
#pragma unroll
        for (int mt = 0; mt < 4; mt++) {
            int row = wm * 64 + mt * 16 + g;
#pragma unroll
            for (int nt = 0; nt < 4; nt++) {
                int col = wn * 32 + nt * 8 + t2;
                bn[row * 133 + col]           = fmaf(acc[mt][nt][0] + ob, rs, rb);
                bn[row * 133 + col + 1]       = fmaf(acc[mt][nt][1] + ob, rs, rb);
                bn[(row + 8) * 133 + col]     = fmaf(acc[mt][nt][2] + ob, rs, rb);
                bn[(row + 8) * 133 + col + 1] = fmaf(acc[mt][nt][3] + ob, rs, rb);
            }
        }
        __syncthreads();
        // coalesced NCHW write with fused residual + relu
        const int spl = tid & 127, coh = tid >> 7;
        const int sp = sp0 + spl;
        const int n2 = sp / NHW, hw2 = sp - n2 * NHW;
        const size_t base = ((size_t)n2 * 1024 + co0) * NHW + hw2;
#pragma unroll 4
        for (int it = 0; it < 64; it++) {
            int c = it * 2 + coh;
            float v = bn[spl * 133 + c];
            size_t adr = base + (size_t)c * NHW;
            out[adr] = fmaxf(v + xres[adr], 0.f);
        }
    }
}

// ---------------- launch ----------------
extern "C" void kernel_launch(void* const* d_in, const int* in_sizes, int n_in,
                              void* d_out, int out_size) {
    const float* x   = (const float*)d_in[0];
    const float* w1  = (const float*)d_in[1];
    const float* w2  = (const float*)d_in[2];
    const float* w3  = (const float*)d_in[3];
    const float* b1b = (const float*)d_in[4];
    const float* b2a = (const float*)d_in[5];
    const float* b2b = (const float*)d_in[6];
    const float* b3a = (const float*)d_in[7];
    const float* b3b = (const float*)d_in[8];
    const float* rsc = (const float*)d_in[9];
    const float* rbi = (const float*)d_in[10];
    float* out = (float*)d_out;

    float *xt, *o1, *o2, *w2t;
    cudaGetSymbolAddress((void**)&xt, g_xt);
    cudaGetSymbolAddress((void**)&o1, g_o1);
    cudaGetSymbolAddress((void**)&o2, g_o2);
    cudaGetSymbolAddress((void**)&w2t, g_w2t);

    cudaFuncSetAttribute(conv_mma<1>, cudaFuncAttributeMaxDynamicSharedMemorySize, SMEM_BYTES);
    cudaFuncSetAttribute(conv_mma<2>, cudaFuncAttributeMaxDynamicSharedMemorySize, SMEM_BYTES);
    cudaFuncSetAttribute(conv_mma<3>, cudaFuncAttributeMaxDynamicSharedMemorySize, SMEM_BYTES);

    transpose_x<<<dim3(7, 32, 128), dim3(32, 8)>>>(x, xt);
    transpose_w2<<<2304, 256>>>(w2, w2t);

    // conv1: 1x1 1024->256; o1 = conv + b1b + b2a (NHWC)
    conv_mma<1><<<392, 256, SMEM_BYTES>>>(xt, w1, o1, nullptr, b1b, b2a, nullptr);
    // conv2: 3x3 pad1 256->256; o2 = conv + b2b + b3a (NHWC)
    conv_mma<2><<<392, 256, SMEM_BYTES>>>(o1, w2t, o2, nullptr, b2b, b3a, nullptr);
    // conv3: 1x1 256->1024; out NCHW = relu((conv + b3b)*rs + rb + x)
    conv_mma<3><<<1568, 256, SMEM_BYTES>>>(o2, w3, out, x, b3b, rsc, rbi);
}